// round 2
// baseline (speedup 1.0000x reference)
#include <cuda_runtime.h>
#include <math.h>

#define B_   8
#define L_   4096
#define D_   768
#define MTOT (B_ * L_)      // 32768
#define N2   (2 * D_)       // 1536
#define CL   256
#define NC   (L_ / CL)      // 16

// ---------------- scratch (device globals; no allocations allowed) ----------
__device__ float g_xn[(size_t)MTOT * D_];   // layernorm out; reused as yb after GEMM1
__device__ float g_xg[(size_t)MTOT * D_];   // gate branch input
__device__ float g_zg[(size_t)MTOT * D_];   // silu(z)
__device__ float g_fc[(size_t)MTOT * D_];   // forward conv out
__device__ float g_bc[(size_t)MTOT * D_];   // backward conv out (un-flipped coords)
__device__ float g_yc[(size_t)MTOT * D_];   // combined gated output
__device__ float g_Wc[3 * D_ * N2];         // combined conv weights [slab][i][n]
__device__ float g_biasc[N2];
__device__ float g_carryF[B_ * NC * D_];
__device__ float g_carryB[B_ * NC * D_];
__device__ float g_HinF[B_ * NC * D_];
__device__ float g_HinB[B_ * NC * D_];

__device__ __forceinline__ float sigmoidf_(float x) { return 1.f / (1.f + expf(-x)); }

// ---------------- layernorm ----------------
__global__ void __launch_bounds__(256) ln_kernel(const float* __restrict__ x,
                                                 const float* __restrict__ g,
                                                 const float* __restrict__ b) {
    int row = blockIdx.x;
    const float* xr = x + (size_t)row * D_;
    int tid = threadIdx.x;
    float v0 = xr[tid], v1 = xr[tid + 256], v2 = xr[tid + 512];
    float s  = v0 + v1 + v2;
    float ss = v0 * v0 + v1 * v1 + v2 * v2;
    #pragma unroll
    for (int o = 16; o; o >>= 1) {
        s  += __shfl_xor_sync(0xffffffffu, s, o);
        ss += __shfl_xor_sync(0xffffffffu, ss, o);
    }
    __shared__ float sm[2][8];
    int w = tid >> 5;
    if ((tid & 31) == 0) { sm[0][w] = s; sm[1][w] = ss; }
    __syncthreads();
    float st = 0.f, sst = 0.f;
    #pragma unroll
    for (int i = 0; i < 8; i++) { st += sm[0][i]; sst += sm[1][i]; }
    float mu  = st * (1.f / 768.f);
    float var = sst * (1.f / 768.f) - mu * mu;
    float inv = rsqrtf(var + 1e-5f);
    float* o = g_xn + (size_t)row * D_;
    o[tid]       = (v0 - mu) * inv * g[tid]       + b[tid];
    o[tid + 256] = (v1 - mu) * inv * g[tid + 256] + b[tid + 256];
    o[tid + 512] = (v2 - mu) * inv * g[tid + 512] + b[tid + 512];
}

// ---------------- weight prep: Wc[slab][i][n]  (fwd n<768, bwd reversed-k n>=768)
__global__ void prep_kernel(const float* __restrict__ Wf, const float* __restrict__ Wb,
                            const float* __restrict__ bfc, const float* __restrict__ bbc) {
    int gtid = blockIdx.x * blockDim.x + threadIdx.x;
    if (gtid < N2) g_biasc[gtid] = (gtid < D_) ? bfc[gtid] : bbc[gtid - D_];
    int total = 3 * D_ * N2;
    for (int idx = gtid; idx < total; idx += gridDim.x * blockDim.x) {
        int slab = idx / (D_ * N2);
        int rem  = idx - slab * (D_ * N2);
        int i = rem / N2;
        int n = rem - i * N2;
        float v;
        if (n < D_) v = Wf[((size_t)n * D_ + i) * 3 + slab];
        else        v = Wb[((size_t)(n - D_) * D_ + i) * 3 + (2 - slab)];
        g_Wc[idx] = v;
    }
}

// ---------------- generic SGEMM 128x128x8, 8x8 per thread ----------------
// MODE 0: proj epilogue (split -> g_xg, silu -> g_zg)
// MODE 2: out epilogue (bias + residual -> C)
template <int MODE>
__global__ void __launch_bounds__(256) sgemm_kernel(
        const float* __restrict__ A, const float* __restrict__ Bm,
        const float* __restrict__ bias, const float* __restrict__ add,
        float* __restrict__ C, int N, int K) {
    __shared__ float As[8][128];
    __shared__ float Bs[8][128];
    int tid = threadIdx.x;
    int arow = tid >> 1, acol = (tid & 1) << 2;
    int brow = tid >> 5, bcol = (tid & 31) << 2;
    int grow = blockIdx.y * 128 + arow;
    const float* Ap = A + (size_t)grow * K + acol;
    const float* Bp = Bm + (size_t)brow * N + blockIdx.x * 128 + bcol;
    int tx = tid & 15, ty = tid >> 4;
    float acc[8][8];
    #pragma unroll
    for (int i = 0; i < 8; i++)
        #pragma unroll
        for (int j = 0; j < 8; j++) acc[i][j] = 0.f;

    for (int k0 = 0; k0 < K; k0 += 8) {
        float4 a4 = *(const float4*)(Ap + k0);
        float4 b4 = *(const float4*)(Bp + (size_t)k0 * N);
        __syncthreads();
        As[acol + 0][arow] = a4.x; As[acol + 1][arow] = a4.y;
        As[acol + 2][arow] = a4.z; As[acol + 3][arow] = a4.w;
        *(float4*)&Bs[brow][bcol] = b4;
        __syncthreads();
        #pragma unroll
        for (int kk = 0; kk < 8; kk++) {
            float4 x0 = *(const float4*)&As[kk][ty * 8];
            float4 x1 = *(const float4*)&As[kk][ty * 8 + 4];
            float4 y0 = *(const float4*)&Bs[kk][tx * 8];
            float4 y1 = *(const float4*)&Bs[kk][tx * 8 + 4];
            float ar[8] = {x0.x, x0.y, x0.z, x0.w, x1.x, x1.y, x1.z, x1.w};
            float br[8] = {y0.x, y0.y, y0.z, y0.w, y1.x, y1.y, y1.z, y1.w};
            #pragma unroll
            for (int i = 0; i < 8; i++)
                #pragma unroll
                for (int j = 0; j < 8; j++)
                    acc[i][j] = fmaf(ar[i], br[j], acc[i][j]);
        }
    }
    int colBase = blockIdx.x * 128 + tx * 8;
    int rowBase = blockIdx.y * 128 + ty * 8;
    #pragma unroll
    for (int i = 0; i < 8; i++) {
        int row = rowBase + i;
        #pragma unroll
        for (int j = 0; j < 8; j++) {
            int col = colBase + j;
            float v = acc[i][j] + bias[col];
            if (MODE == 0) {
                if (col < D_) g_xg[(size_t)row * D_ + col] = v;
                else          g_zg[(size_t)row * D_ + (col - D_)] = v / (1.f + expf(-v));
            } else {
                C[(size_t)row * N + col] = v + add[(size_t)row * N + col];
            }
        }
    }
}

// ---------------- fused dual-direction conv as shifted GEMM (K = 3 x 768) ----
__global__ void __launch_bounds__(256) conv_gemm_kernel(const float* __restrict__ A) {
    __shared__ float As[8][128];
    __shared__ float Bs[8][128];
    const int N = N2, K = D_;
    int tid = threadIdx.x;
    int arow = tid >> 1, acol = (tid & 1) << 2;
    int brow = tid >> 5, bcol = (tid & 31) << 2;
    int grow = blockIdx.y * 128 + arow;
    int t = grow & (L_ - 1);
    int tx = tid & 15, ty = tid >> 4;
    float acc[8][8];
    #pragma unroll
    for (int i = 0; i < 8; i++)
        #pragma unroll
        for (int j = 0; j < 8; j++) acc[i][j] = 0.f;

    for (int slab = 0; slab < 3; slab++) {
        int dk = slab - 1;
        bool valid = ((unsigned)(t + dk) < (unsigned)L_);
        const float* Ap = A + (size_t)(grow + dk) * K + acol;
        const float* Bp = g_Wc + (size_t)slab * K * N + (size_t)brow * N + blockIdx.x * 128 + bcol;
        for (int k0 = 0; k0 < K; k0 += 8) {
            float4 a4 = valid ? *(const float4*)(Ap + k0) : make_float4(0.f, 0.f, 0.f, 0.f);
            float4 b4 = *(const float4*)(Bp + (size_t)k0 * N);
            __syncthreads();
            As[acol + 0][arow] = a4.x; As[acol + 1][arow] = a4.y;
            As[acol + 2][arow] = a4.z; As[acol + 3][arow] = a4.w;
            *(float4*)&Bs[brow][bcol] = b4;
            __syncthreads();
            #pragma unroll
            for (int kk = 0; kk < 8; kk++) {
                float4 x0 = *(const float4*)&As[kk][ty * 8];
                float4 x1 = *(const float4*)&As[kk][ty * 8 + 4];
                float4 y0 = *(const float4*)&Bs[kk][tx * 8];
                float4 y1 = *(const float4*)&Bs[kk][tx * 8 + 4];
                float ar[8] = {x0.x, x0.y, x0.z, x0.w, x1.x, x1.y, x1.z, x1.w};
                float br[8] = {y0.x, y0.y, y0.z, y0.w, y1.x, y1.y, y1.z, y1.w};
                #pragma unroll
                for (int i = 0; i < 8; i++)
                    #pragma unroll
                    for (int j = 0; j < 8; j++)
                        acc[i][j] = fmaf(ar[i], br[j], acc[i][j]);
            }
        }
    }
    int colBase = blockIdx.x * 128 + tx * 8;
    int rowBase = blockIdx.y * 128 + ty * 8;
    #pragma unroll
    for (int i = 0; i < 8; i++) {
        int row = rowBase + i;
        #pragma unroll
        for (int j = 0; j < 8; j++) {
            int col = colBase + j;
            float v = acc[i][j] + g_biasc[col];
            if (col < D_) g_fc[(size_t)row * D_ + col] = v;
            else          g_bc[(size_t)row * D_ + (col - D_)] = v;
        }
    }
}

// ---------------- chunked SSM scan: phase 1 (local scans, both directions) ---
__global__ void __launch_bounds__(256) scan_phase1(
        const float* __restrict__ af, const float* __restrict__ bf,
        const float* __restrict__ cf, const float* __restrict__ df,
        const float* __restrict__ ab, const float* __restrict__ bbp,
        const float* __restrict__ cb, const float* __restrict__ db) {
    int d   = blockIdx.x * 256 + threadIdx.x;
    int c   = blockIdx.y;
    int dir = blockIdx.z & 1;
    int b   = blockIdx.z >> 1;
    size_t base = ((size_t)b * L_ + (size_t)c * CL) * D_ + d;
    if (dir == 0) {
        float a  = sigmoidf_(af[d]);
        float bp = bf[d], cp = cf[d], dp = df[d];
        float h = 0.f;
        size_t idx = base;
        #pragma unroll 4
        for (int l = 0; l < CL; l++, idx += D_) {
            float u = g_fc[idx];
            h = fmaf(a, h, bp * u);
            g_yc[idx] = fmaf(cp, h, dp * u);
        }
        g_carryF[((size_t)b * NC + c) * D_ + d] = h;
    } else {
        float a  = sigmoidf_(ab[d]);
        float bp = bbp[d], cp = cb[d], dp = db[d];
        float h = 0.f;
        size_t idx = base + (size_t)(CL - 1) * D_;
        #pragma unroll 4
        for (int l = 0; l < CL; l++, idx -= D_) {
            float u = g_bc[idx];
            h = fmaf(a, h, bp * u);
            g_xn[idx] = fmaf(cp, h, dp * u);   // xn is dead; reuse as yb buffer
        }
        g_carryB[((size_t)b * NC + c) * D_ + d] = h;
    }
}

// ---------------- phase 2: combine chunk carries (tiny) ----------------------
__global__ void __launch_bounds__(256) scan_phase2(const float* __restrict__ af,
                                                   const float* __restrict__ ab) {
    int d = blockIdx.x * 256 + threadIdx.x;
    int b = blockIdx.y;
    float a1 = sigmoidf_(af[d]);
    float aCL1 = powf(a1, (float)CL);
    float H = 0.f;
    for (int c = 0; c < NC; c++) {
        size_t i = ((size_t)b * NC + c) * D_ + d;
        g_HinF[i] = H;
        H = aCL1 * H + g_carryF[i];
    }
    float a2 = sigmoidf_(ab[d]);
    float aCL2 = powf(a2, (float)CL);
    H = 0.f;
    for (int c = NC - 1; c >= 0; c--) {
        size_t i = ((size_t)b * NC + c) * D_ + d;
        g_HinB[i] = H;
        H = aCL2 * H + g_carryB[i];
    }
}

// ---------------- phase 3: fixup + silu-gate combine -------------------------
__global__ void __launch_bounds__(256) scan_phase3(
        const float* __restrict__ af, const float* __restrict__ cf,
        const float* __restrict__ ab, const float* __restrict__ cb) {
    int d = blockIdx.x * 256 + threadIdx.x;
    int c = blockIdx.y;
    int b = blockIdx.z;
    float a1 = sigmoidf_(af[d]);
    float a2 = sigmoidf_(ab[d]);
    float la1 = logf(a1);
    size_t ci = ((size_t)b * NC + c) * D_ + d;
    float HF = g_HinF[ci] * cf[d];
    float HB = g_HinB[ci] * cb[d];
    size_t base = ((size_t)b * L_ + (size_t)c * CL) * D_ + d;
    float pb = 1.f;
    size_t idx = base + (size_t)(CL - 1) * D_;
    for (int l = CL - 1; l >= 0; l--, idx -= D_) {
        pb *= a2;                               // a2^(CL - l)
        float pf = expf((float)(l + 1) * la1);  // a1^(l+1), underflow-safe
        float yf = g_yc[idx] + pf * HF;
        float yb = g_xn[idx] + pb * HB;
        g_yc[idx] = (yf + yb) * g_zg[idx];
    }
}

// ---------------- launch ----------------
extern "C" void kernel_launch(void* const* d_in, const int* in_sizes, int n_in,
                              void* d_out, int out_size) {
    const float* x    = (const float*)d_in[0];
    const float* ln_g = (const float*)d_in[1];
    const float* ln_b = (const float*)d_in[2];
    const float* Wi   = (const float*)d_in[3];
    const float* bi   = (const float*)d_in[4];
    const float* Wf   = (const float*)d_in[5];
    const float* bfc  = (const float*)d_in[6];
    const float* af   = (const float*)d_in[7];
    const float* bf   = (const float*)d_in[8];
    const float* cf   = (const float*)d_in[9];
    const float* df   = (const float*)d_in[10];
    const float* Wb   = (const float*)d_in[11];
    const float* bbc  = (const float*)d_in[12];
    const float* ab   = (const float*)d_in[13];
    const float* bb   = (const float*)d_in[14];
    const float* cb   = (const float*)d_in[15];
    const float* db   = (const float*)d_in[16];
    const float* Wo   = (const float*)d_in[17];
    const float* bo   = (const float*)d_in[18];
    float* out = (float*)d_out;

    float *p_xn, *p_xg, *p_yc;
    cudaGetSymbolAddress((void**)&p_xn, g_xn);
    cudaGetSymbolAddress((void**)&p_xg, g_xg);
    cudaGetSymbolAddress((void**)&p_yc, g_yc);

    ln_kernel<<<MTOT, 256>>>(x, ln_g, ln_b);
    prep_kernel<<<2048, 256>>>(Wf, Wb, bfc, bbc);

    // proj: xn @ Wi + bi  -> xg | silu(z)
    sgemm_kernel<0><<<dim3(N2 / 128, MTOT / 128), 256>>>(p_xn, Wi, bi, nullptr, nullptr, N2, D_);

    // both convs as one shifted GEMM over K = 3*768
    conv_gemm_kernel<<<dim3(N2 / 128, MTOT / 128), 256>>>(p_xg);

    // chunked scans
    scan_phase1<<<dim3(D_ / 256, NC, B_ * 2), 256>>>(af, bf, cf, df, ab, bb, cb, db);
    scan_phase2<<<dim3(D_ / 256, B_), 256>>>(af, ab);
    scan_phase3<<<dim3(D_ / 256, NC, B_), 256>>>(af, cf, ab, cb);

    // out: yc @ Wo + bo + residual
    sgemm_kernel<2><<<dim3(D_ / 128, MTOT / 128), 256>>>(p_yc, Wo, bo, x, out, D_, D_);
}

// round 4
// speedup vs baseline: 4.6243x; 4.6243x over previous
#include <cuda_runtime.h>
#include <cuda_fp16.h>
#include <math.h>
#include <stdint.h>

#define B_   8
#define L_   4096
#define D_   768
#define MTOT (B_ * L_)      // 32768
#define N2   1536
#define KC   2304           // conv K = 3 * 768
#define CL   256
#define NC   (L_ / CL)      // 16

// ---------------- scratch (device globals) ----------------
__device__ __align__(256) __half g_xn_h[(size_t)MTOT * D_];
__device__ __align__(256) __half g_xg_h[(size_t)MTOT * D_];
__device__ __align__(256) __half g_yc_h[(size_t)MTOT * D_];
__device__ __align__(256) float  g_zg [(size_t)MTOT * D_];
__device__ __align__(256) float  g_fc [(size_t)MTOT * D_];
__device__ __align__(256) float  g_bc [(size_t)MTOT * D_];
__device__ __align__(256) float  g_yf [(size_t)MTOT * D_];
__device__ __align__(256) float  g_yb [(size_t)MTOT * D_];
__device__ __align__(256) __half g_WiT[(size_t)N2 * D_];
__device__ __align__(256) __half g_WcT[(size_t)N2 * KC];
__device__ __align__(256) __half g_WoT[(size_t)D_ * D_];
__device__ float g_biasc[N2];
__device__ float g_carryF[B_ * NC * D_];
__device__ float g_carryB[B_ * NC * D_];
__device__ float g_HinF[B_ * NC * D_];
__device__ float g_HinB[B_ * NC * D_];

__device__ __forceinline__ float sigmoidf_(float x) { return 1.f / (1.f + expf(-x)); }

// ---------------- ptx helpers (sm_80-era ISA only; no arch-'a' features) -----
__device__ __forceinline__ uint32_t s2u(const void* p) {
    uint32_t a;
    asm("{ .reg .u64 t; cvta.to.shared.u64 t, %1; cvt.u32.u64 %0, t; }" : "=r"(a) : "l"(p));
    return a;
}
__device__ __forceinline__ void ldm_x4(uint32_t* r, uint32_t addr) {
    asm volatile("ldmatrix.sync.aligned.m8n8.x4.shared.b16 {%0,%1,%2,%3}, [%4];"
                 : "=r"(r[0]), "=r"(r[1]), "=r"(r[2]), "=r"(r[3]) : "r"(addr));
}
__device__ __forceinline__ void mma16816(float* c, const uint32_t* a, uint32_t b0, uint32_t b1) {
    asm volatile("mma.sync.aligned.m16n8k16.row.col.f32.f16.f16.f32 "
        "{%0,%1,%2,%3}, {%4,%5,%6,%7}, {%8,%9}, {%0,%1,%2,%3};"
        : "+f"(c[0]), "+f"(c[1]), "+f"(c[2]), "+f"(c[3])
        : "r"(a[0]), "r"(a[1]), "r"(a[2]), "r"(a[3]), "r"(b0), "r"(b1));
}
__device__ __forceinline__ void cp16(uint32_t dst, const void* src, bool pred) {
    if (pred)
        asm volatile("cp.async.cg.shared.global [%0], [%1], 16;" :: "r"(dst), "l"(src));
    else
        asm volatile("st.shared.v4.b32 [%0], {%1,%1,%1,%1};" :: "r"(dst), "r"(0u));
}
#define CP_COMMIT() asm volatile("cp.async.commit_group;" ::: "memory")
#define CP_WAIT1()  asm volatile("cp.async.wait_group 1;" ::: "memory")
#define CP_WAIT0()  asm volatile("cp.async.wait_group 0;" ::: "memory")

// ---------------- layernorm (writes fp16) ----------------
__global__ void __launch_bounds__(256) ln_kernel(const float* __restrict__ x,
                                                 const float* __restrict__ g,
                                                 const float* __restrict__ b) {
    int row = blockIdx.x;
    const float* xr = x + (size_t)row * D_;
    int tid = threadIdx.x;
    float v0 = xr[tid], v1 = xr[tid + 256], v2 = xr[tid + 512];
    float s = v0 + v1 + v2;
    float ss = v0 * v0 + v1 * v1 + v2 * v2;
    #pragma unroll
    for (int o = 16; o; o >>= 1) {
        s  += __shfl_xor_sync(0xffffffffu, s, o);
        ss += __shfl_xor_sync(0xffffffffu, ss, o);
    }
    __shared__ float sm[2][8];
    int w = tid >> 5;
    if ((tid & 31) == 0) { sm[0][w] = s; sm[1][w] = ss; }
    __syncthreads();
    float st = 0.f, sst = 0.f;
    #pragma unroll
    for (int i = 0; i < 8; i++) { st += sm[0][i]; sst += sm[1][i]; }
    float mu = st * (1.f / 768.f);
    float var = sst * (1.f / 768.f) - mu * mu;
    float inv = rsqrtf(var + 1e-5f);
    __half* o = g_xn_h + (size_t)row * D_;
    o[tid]       = __float2half_rn((v0 - mu) * inv * g[tid]       + b[tid]);
    o[tid + 256] = __float2half_rn((v1 - mu) * inv * g[tid + 256] + b[tid + 256]);
    o[tid + 512] = __float2half_rn((v2 - mu) * inv * g[tid + 512] + b[tid + 512]);
}

// ---------------- weight prep: transpose + fp16 ----------------
__global__ void prep_kernel(const float* __restrict__ Wi, const float* __restrict__ Wf,
                            const float* __restrict__ Wb, const float* __restrict__ Wo,
                            const float* __restrict__ bfc, const float* __restrict__ bbc) {
    int gtid = blockIdx.x * blockDim.x + threadIdx.x;
    int stride = gridDim.x * blockDim.x;
    if (gtid < N2) g_biasc[gtid] = (gtid < D_) ? bfc[gtid] : bbc[gtid - D_];
    for (int idx = gtid; idx < N2 * D_; idx += stride) {     // WiT[n][k] = Wi[k][n]
        int n = idx / D_, k = idx - n * D_;
        g_WiT[idx] = __float2half_rn(Wi[(size_t)k * N2 + n]);
    }
    for (int idx = gtid; idx < N2 * KC; idx += stride) {     // WcT[n][s*768+i]
        int n = idx / KC, r = idx - n * KC;
        int s = r / D_, i = r - s * D_;
        float v;
        if (n < D_) v = Wf[((size_t)n * D_ + i) * 3 + s];
        else        v = Wb[((size_t)(n - D_) * D_ + i) * 3 + (2 - s)];
        g_WcT[idx] = __float2half_rn(v);
    }
    for (int idx = gtid; idx < D_ * D_; idx += stride) {     // WoT[n][k] = Wo[k][n]
        int n = idx / D_, k = idx - n * D_;
        g_WoT[idx] = __float2half_rn(Wo[(size_t)k * D_ + n]);
    }
}

// ---------------- HMMA GEMM: CTA 128x128, K-chunk 32, 8 warps (32x64 each) ---
// A [M,K] fp16 row-major, BT [N,K] fp16 row-major, fp32 accum.
// MODE 0: proj -> g_xg_h | silu -> g_zg
// MODE 1: conv (slab-shifted A, K=2304) -> g_fc | g_bc
// MODE 2: out  -> +bias +residual -> Cout
#define LDS 40                    // halves per smem row (32 data + 8 pad = 80B)
#define A_OFF(s) ((s) * 5120)     // in halves
#define B_OFF(s) (10240 + (s) * 5120)
#define SMEM_BYTES 40960

template <int MODE>
__global__ void __launch_bounds__(256, 2) hmma_gemm(
        const __half* __restrict__ A, const __half* __restrict__ BT,
        const float* __restrict__ bias, const float* __restrict__ resid,
        float* __restrict__ Cout, int Ktot) {
    extern __shared__ __half smh[];
    uint32_t sb = s2u(smh);
    int tid = threadIdx.x, lane = tid & 31, wid = tid >> 5;
    int wm = wid & 3, wn = wid >> 2;
    int mtile = blockIdx.y, ntile = blockIdx.x;

    float acc[2][8][4];
    #pragma unroll
    for (int a = 0; a < 2; a++)
        #pragma unroll
        for (int b2 = 0; b2 < 8; b2++)
            #pragma unroll
            for (int c = 0; c < 4; c++) acc[a][b2][c] = 0.f;

    const int NCH = Ktot >> 5;

    // -------- tile loader --------
    auto load_tile = [&](int s, int jc) {
        int k0 = jc << 5;
        int dk = 0, kk0 = k0;
        if (MODE == 1) { int slab = k0 / D_; dk = slab - 1; kk0 = k0 - slab * D_; }
        #pragma unroll
        for (int i = 0; i < 2; i++) {
            int u = tid + (i << 8);
            int r = u >> 2, c8 = (u & 3) << 3;       // 8-half (16B) column offset
            // A row
            int grow = mtile * 128 + r;
            bool ok = true;
            const __half* srcA;
            if (MODE == 1) {
                int t = grow & (L_ - 1);
                ok = ((unsigned)(t + dk) < (unsigned)L_);
                srcA = A + (size_t)(grow + dk) * D_ + kk0 + c8;
            } else {
                srcA = A + (size_t)grow * D_ + k0 + c8;
            }
            cp16(sb + (uint32_t)(A_OFF(s) + r * LDS + c8) * 2, srcA, ok);
            // B row
            const __half* srcB = BT + (size_t)(ntile * 128 + r) * Ktot + k0 + c8;
            cp16(sb + (uint32_t)(B_OFF(s) + r * LDS + c8) * 2, srcB, true);
        }
        CP_COMMIT();
    };

    // -------- main pipeline --------
    load_tile(0, 0);
    for (int jc = 0; jc < NCH; jc++) {
        int s = jc & 1;
        if (jc + 1 < NCH) { load_tile(s ^ 1, jc + 1); CP_WAIT1(); }
        else              { CP_WAIT0(); }
        __syncthreads();
        #pragma unroll
        for (int kk = 0; kk < 32; kk += 16) {
            uint32_t af[2][4], bf[4][4];
            int rsel = lane & 15, csel = kk + ((lane >> 4) << 3);
            #pragma unroll
            for (int mt = 0; mt < 2; mt++)
                ldm_x4(af[mt], sb + (uint32_t)(A_OFF(s) + (wm * 32 + mt * 16 + rsel) * LDS + csel) * 2);
            #pragma unroll
            for (int g = 0; g < 4; g++)
                ldm_x4(bf[g], sb + (uint32_t)(B_OFF(s) + (wn * 64 + g * 16 + rsel) * LDS + csel) * 2);
            #pragma unroll
            for (int mt = 0; mt < 2; mt++)
                #pragma unroll
                for (int j = 0; j < 8; j++)
                    mma16816(acc[mt][j], af[mt], bf[j >> 1][j & 1], bf[j >> 1][(j & 1) + 2]);
        }
        __syncthreads();
    }

    // -------- epilogue --------
    int nb = ntile * 128 + wn * 64;
    int mb = mtile * 128 + wm * 32;
    #pragma unroll
    for (int mt = 0; mt < 2; mt++) {
        #pragma unroll
        for (int j = 0; j < 8; j++) {
            int colg = nb + j * 8 + ((lane & 3) << 1);
            int r0 = mb + mt * 16 + (lane >> 2);
            int r1 = r0 + 8;
            float b0 = bias[colg], b1 = bias[colg + 1];
            float v00 = acc[mt][j][0] + b0, v01 = acc[mt][j][1] + b1;
            float v10 = acc[mt][j][2] + b0, v11 = acc[mt][j][3] + b1;
            if (MODE == 0) {
                if (colg < D_) {
                    *(__half2*)(g_xg_h + (size_t)r0 * D_ + colg) = __floats2half2_rn(v00, v01);
                    *(__half2*)(g_xg_h + (size_t)r1 * D_ + colg) = __floats2half2_rn(v10, v11);
                } else {
                    int cz = colg - D_;
                    float2 z0 = make_float2(v00 / (1.f + expf(-v00)), v01 / (1.f + expf(-v01)));
                    float2 z1 = make_float2(v10 / (1.f + expf(-v10)), v11 / (1.f + expf(-v11)));
                    *(float2*)(g_zg + (size_t)r0 * D_ + cz) = z0;
                    *(float2*)(g_zg + (size_t)r1 * D_ + cz) = z1;
                }
            } else if (MODE == 1) {
                if (colg < D_) {
                    *(float2*)(g_fc + (size_t)r0 * D_ + colg) = make_float2(v00, v01);
                    *(float2*)(g_fc + (size_t)r1 * D_ + colg) = make_float2(v10, v11);
                } else {
                    int cz = colg - D_;
                    *(float2*)(g_bc + (size_t)r0 * D_ + cz) = make_float2(v00, v01);
                    *(float2*)(g_bc + (size_t)r1 * D_ + cz) = make_float2(v10, v11);
                }
            } else {
                float2 a0 = *(const float2*)(resid + (size_t)r0 * D_ + colg);
                float2 a1 = *(const float2*)(resid + (size_t)r1 * D_ + colg);
                *(float2*)(Cout + (size_t)r0 * D_ + colg) = make_float2(v00 + a0.x, v01 + a0.y);
                *(float2*)(Cout + (size_t)r1 * D_ + colg) = make_float2(v10 + a1.x, v11 + a1.y);
            }
        }
    }
}

// ---------------- chunked SSM scans ----------------
__global__ void __launch_bounds__(256) scan_phase1(
        const float* __restrict__ af, const float* __restrict__ bf,
        const float* __restrict__ cf, const float* __restrict__ df,
        const float* __restrict__ ab, const float* __restrict__ bbp,
        const float* __restrict__ cb, const float* __restrict__ db) {
    int d = blockIdx.x * 256 + threadIdx.x;
    int c = blockIdx.y;
    int dir = blockIdx.z & 1;
    int b = blockIdx.z >> 1;
    size_t base = ((size_t)b * L_ + (size_t)c * CL) * D_ + d;
    if (dir == 0) {
        float a = sigmoidf_(af[d]);
        float bp = bf[d], cp = cf[d], dp = df[d];
        float h = 0.f;
        size_t idx = base;
        #pragma unroll 4
        for (int l = 0; l < CL; l++, idx += D_) {
            float u = g_fc[idx];
            h = fmaf(a, h, bp * u);
            g_yf[idx] = fmaf(cp, h, dp * u);
        }
        g_carryF[((size_t)b * NC + c) * D_ + d] = h;
    } else {
        float a = sigmoidf_(ab[d]);
        float bp = bbp[d], cp = cb[d], dp = db[d];
        float h = 0.f;
        size_t idx = base + (size_t)(CL - 1) * D_;
        #pragma unroll 4
        for (int l = 0; l < CL; l++, idx -= D_) {
            float u = g_bc[idx];
            h = fmaf(a, h, bp * u);
            g_yb[idx] = fmaf(cp, h, dp * u);
        }
        g_carryB[((size_t)b * NC + c) * D_ + d] = h;
    }
}

__global__ void __launch_bounds__(256) scan_phase2(const float* __restrict__ af,
                                                   const float* __restrict__ ab) {
    int d = blockIdx.x * 256 + threadIdx.x;
    int b = blockIdx.y;
    float a1 = sigmoidf_(af[d]);
    float aCL1 = powf(a1, (float)CL);
    float H = 0.f;
    for (int c = 0; c < NC; c++) {
        size_t i = ((size_t)b * NC + c) * D_ + d;
        g_HinF[i] = H;
        H = aCL1 * H + g_carryF[i];
    }
    float a2 = sigmoidf_(ab[d]);
    float aCL2 = powf(a2, (float)CL);
    H = 0.f;
    for (int c = NC - 1; c >= 0; c--) {
        size_t i = ((size_t)b * NC + c) * D_ + d;
        g_HinB[i] = H;
        H = aCL2 * H + g_carryB[i];
    }
}

__global__ void __launch_bounds__(256) scan_phase3b(const float* __restrict__ ab,
                                                    const float* __restrict__ cb) {
    int d = blockIdx.x * 256 + threadIdx.x;
    int c = blockIdx.y;
    int b = blockIdx.z;
    float a2 = sigmoidf_(ab[d]);
    size_t ci = ((size_t)b * NC + c) * D_ + d;
    float HB = g_HinB[ci] * cb[d];
    size_t idx = ((size_t)b * L_ + (size_t)c * CL + (CL - 1)) * D_ + d;
    float pb = 1.f;
    #pragma unroll 4
    for (int l = CL - 1; l >= 0; l--, idx -= D_) {
        pb *= a2;
        g_yb[idx] += pb * HB;
    }
}

__global__ void __launch_bounds__(256) scan_phase3c(const float* __restrict__ af,
                                                    const float* __restrict__ cf) {
    int d = blockIdx.x * 256 + threadIdx.x;
    int c = blockIdx.y;
    int b = blockIdx.z;
    float a1 = sigmoidf_(af[d]);
    size_t ci = ((size_t)b * NC + c) * D_ + d;
    float HF = g_HinF[ci] * cf[d];
    size_t idx = ((size_t)b * L_ + (size_t)c * CL) * D_ + d;
    float pf = 1.f;
    #pragma unroll 4
    for (int l = 0; l < CL; l++, idx += D_) {
        pf *= a1;
        float y = (g_yf[idx] + pf * HF + g_yb[idx]) * g_zg[idx];
        g_yc_h[idx] = __float2half_rn(y);
    }
}

// ---------------- launch ----------------
extern "C" void kernel_launch(void* const* d_in, const int* in_sizes, int n_in,
                              void* d_out, int out_size) {
    const float* x    = (const float*)d_in[0];
    const float* ln_g = (const float*)d_in[1];
    const float* ln_b = (const float*)d_in[2];
    const float* Wi   = (const float*)d_in[3];
    const float* bi   = (const float*)d_in[4];
    const float* Wf   = (const float*)d_in[5];
    const float* bfc  = (const float*)d_in[6];
    const float* af   = (const float*)d_in[7];
    const float* bf   = (const float*)d_in[8];
    const float* cf   = (const float*)d_in[9];
    const float* df   = (const float*)d_in[10];
    const float* Wb   = (const float*)d_in[11];
    const float* bbc  = (const float*)d_in[12];
    const float* ab   = (const float*)d_in[13];
    const float* bb   = (const float*)d_in[14];
    const float* cb   = (const float*)d_in[15];
    const float* db   = (const float*)d_in[16];
    const float* Wo   = (const float*)d_in[17];
    const float* bo   = (const float*)d_in[18];
    float* out = (float*)d_out;

    __half *p_xn, *p_xg, *p_yc, *p_WiT, *p_WcT, *p_WoT;
    float *p_biasc;
    cudaGetSymbolAddress((void**)&p_xn, g_xn_h);
    cudaGetSymbolAddress((void**)&p_xg, g_xg_h);
    cudaGetSymbolAddress((void**)&p_yc, g_yc_h);
    cudaGetSymbolAddress((void**)&p_WiT, g_WiT);
    cudaGetSymbolAddress((void**)&p_WcT, g_WcT);
    cudaGetSymbolAddress((void**)&p_WoT, g_WoT);
    cudaGetSymbolAddress((void**)&p_biasc, g_biasc);

    ln_kernel<<<MTOT, 256>>>(x, ln_g, ln_b);
    prep_kernel<<<2048, 256>>>(Wi, Wf, Wb, Wo, bfc, bbc);

    // proj: xn @ Wi + bi -> xg_h | silu(z)
    hmma_gemm<0><<<dim3(N2 / 128, MTOT / 128), 256, SMEM_BYTES>>>(p_xn, p_WiT, bi, nullptr, nullptr, D_);
    // fused dual-direction conv (K = 2304)
    hmma_gemm<1><<<dim3(N2 / 128, MTOT / 128), 256, SMEM_BYTES>>>(p_xg, p_WcT, p_biasc, nullptr, nullptr, KC);
    // scans
    scan_phase1<<<dim3(D_ / 256, NC, B_ * 2), 256>>>(af, bf, cf, df, ab, bb, cb, db);
    scan_phase2<<<dim3(D_ / 256, B_), 256>>>(af, ab);
    scan_phase3b<<<dim3(D_ / 256, NC, B_), 256>>>(ab, cb);
    scan_phase3c<<<dim3(D_ / 256, NC, B_), 256>>>(af, cf);
    // out: yc @ Wo + bo + residual
    hmma_gemm<2><<<dim3(D_ / 128, MTOT / 128), 256, SMEM_BYTES>>>(p_yc, p_WoT, bo, x, out, D_);
}